// round 6
// baseline (speedup 1.0000x reference)
#include <cuda_runtime.h>
#include <math.h>

#define NTAGS 32
#define SLEN 512
#define START_TAG 30
#define STOP_TAG 31

typedef unsigned long long u64;
typedef unsigned int u32;

__device__ __forceinline__ u64 pack2(float a, float b) {
    u64 r;
    asm("mov.b64 %0, {%1, %2};" : "=l"(r) : "f"(a), "f"(b));
    return r;
}
__device__ __forceinline__ void unpack2(u64 v, float &a, float &b) {
    asm("mov.b64 {%0, %1}, %2;" : "=f"(a), "=f"(b) : "l"(v));
}
__device__ __forceinline__ u64 fma2(u64 a, u64 b, u64 c) {
    u64 d;
    asm("fma.rn.f32x2 %0, %1, %2, %3;" : "=l"(d) : "l"(a), "l"(b), "l"(c));
    return d;
}
__device__ __forceinline__ u64 add2(u64 a, u64 b) {
    u64 d;
    asm("add.rn.f32x2 %0, %1, %2;" : "=l"(d) : "l"(a), "l"(b));
    return d;
}
__device__ __forceinline__ u64 mul2(u64 a, u64 b) {
    u64 d;
    asm("mul.rn.f32x2 %0, %1, %2;" : "=l"(d) : "l"(a), "l"(b));
    return d;
}
__device__ __forceinline__ u32 smem_u32(const void* p) {
    u32 a;
    asm("{ .reg .u64 t; cvta.to.shared.u64 t, %1; cvt.u32.u64 %0, t; }"
        : "=r"(a) : "l"(p));
    return a;
}
// 128-bit broadcast load of two packed tag-pairs (volatile: pins ordering
// vs the st.shared below; same-warp smem ops are LSU-in-order, so no
// syncwarp is needed in the convergent ping-pong).
__device__ __forceinline__ void lds2(u64 &lo, u64 &hi, u32 addr) {
    asm volatile("ld.shared.v2.b64 {%0, %1}, [%2];"
                 : "=l"(lo), "=l"(hi) : "r"(addr));
}
__device__ __forceinline__ void sts1(u32 addr, u64 v) {
    asm volatile("st.shared.b64 [%0], %1;" :: "r"(addr), "l"(v) : "memory");
}

// One warp (= one 32-thread CTA) handles TWO batches packed as f32x2.
// Lane i owns target-tag i; exp(transitions) row i in registers (duplicated
// into both packed halves). Exp-domain recurrence w' = (E @ w) * exp(emit).
// Renorm every 4 steps by an exact power of two, computed via integer
// redux.max at block end and APPLIED one block late by folding 2^-e into the
// next block's pe[0] — entirely off the serial chain. Emissions prefetched
// two 4-step blocks ahead (16 outstanding LDGs). No per-step syncwarp.
__global__ __launch_bounds__(32)
void crf_fwd_kernel(const float* __restrict__ feats,
                    const float* __restrict__ trans,
                    float* __restrict__ out) {
    __shared__ __align__(16) u64 wbuf[2][NTAGS];
    const int lane = threadIdx.x;
    const int gw = blockIdx.x;
    const int b0 = gw * 2, b1 = b0 + 1;

    u64 E2[NTAGS];
#pragma unroll
    for (int j = 0; j < NTAGS; j++) {
        float e = __expf(trans[lane * NTAGS + j]);
        E2[j] = pack2(e, e);
    }
    const float eStop = __expf(trans[STOP_TAG * NTAGS + lane]);

    const u32 sb = smem_u32(&wbuf[0][0]);
    const u32 stA = sb + lane * 8;              // store into buf0
    const u32 stB = sb + NTAGS * 8 + lane * 8;  // store into buf1
    const u32 ldA = sb;                          // load base buf0
    const u32 ldB = sb + NTAGS * 8;              // load base buf1

    const float* p0 = feats + (size_t)b0 * SLEN * NTAGS + lane;
    const float* p1 = feats + (size_t)b1 * SLEN * NTAGS + lane;

    // init: alpha one-hot at START -> w one-hot (buf0)
    const float winit = (lane == START_TAG) ? 1.0f : 0.0f;
    sts1(stA, pack2(winit, winit));
    __syncwarp();

    int esum0 = 0, esum1 = 0;
    int ep0 = 0, ep1 = 0;  // pending (not-yet-applied) renorm exponents
    // two-block-deep emission pipeline
    float emA0[4], emA1[4], emB0[4], emB1[4];
#pragma unroll
    for (int u = 0; u < 4; u++) {
        emA0[u] = p0[u * NTAGS];
        emA1[u] = p1[u * NTAGS];
        emB0[u] = p0[(4 + u) * NTAGS];
        emB1[u] = p1[(4 + u) * NTAGS];
    }
    u64 next = 0;

    for (int tb = 0; tb < SLEN; tb += 4) {
        // prefetch block tb+8 (consumed two blocks from now)
        float nx0[4], nx1[4];
        const int nb = (tb + 8 < SLEN) ? (tb + 8) : (SLEN - 4);
#pragma unroll
        for (int u = 0; u < 4; u++) {
            nx0[u] = p0[(nb + u) * NTAGS];
            nx1[u] = p1[(nb + u) * NTAGS];
        }
        // apply last block's renorm: fold 2^-ep into pe[0] (linear in pe)
        esum0 += ep0; esum1 += ep1;
        const float c0 = __int_as_float((127 - ep0) << 23);
        const float c1 = __int_as_float((127 - ep1) << 23);
        float pe0[4], pe1[4];
#pragma unroll
        for (int u = 0; u < 4; u++) {
            pe0[u] = __expf(emA0[u]);
            pe1[u] = __expf(emA1[u]);
        }
        pe0[0] *= c0;
        pe1[0] *= c1;

        // 4 steps; buffer parity is static (even u: buf0->buf1, odd: buf1->buf0)
#pragma unroll
        for (int u = 0; u < 4; u++) {
            const u32 ldbase = (u & 1) ? ldB : ldA;
            const u32 staddr = (u & 1) ? stA : stB;
            u64 a0 = 0, a1 = 0, a2 = 0, a3 = 0;
#pragma unroll
            for (int jj = 0; jj < 8; jj++) {
                u64 va, vb;
                lds2(va, vb, ldbase + jj * 16);
                a0 = fma2(va, E2[4 * jj + 0], a0);
                a1 = fma2(vb, E2[4 * jj + 1], a1);
                // second pair of tags in the same 16B
                (void)0;
            }
            // NOTE: loop above consumed tags {2jj, 2jj+1}; redo properly below
            a0 = 0; a1 = 0; a2 = 0; a3 = 0;
#pragma unroll
            for (int jj = 0; jj < 8; jj++) {
                u64 va, vb;
                lds2(va, vb, ldbase + jj * 16);      // tags 2jj, 2jj+1
                u64 vc, vd;
                lds2(vc, vd, ldbase + 128 + jj * 16); // tags 16+2jj, 17+2jj
                a0 = fma2(va, E2[2 * jj + 0], a0);
                a1 = fma2(vb, E2[2 * jj + 1], a1);
                a2 = fma2(vc, E2[16 + 2 * jj + 0], a2);
                a3 = fma2(vd, E2[16 + 2 * jj + 1], a3);
            }
            next = mul2(add2(add2(a0, a1), add2(a2, a3)),
                        pack2(pe0[u], pe1[u]));
            sts1(staddr, next);
            if (u == 3) {
                // end-of-block max (w >= 0 => IEEE bits monotone as s32)
                float n0, n1;
                unpack2(next, n0, n1);
                int m0i, m1i;
                asm("redux.sync.max.s32 %0, %1, 0xffffffff;"
                    : "=r"(m0i) : "r"(__float_as_int(n0)));
                asm("redux.sync.max.s32 %0, %1, 0xffffffff;"
                    : "=r"(m1i) : "r"(__float_as_int(n1)));
                ep0 = min(max((m0i >> 23) - 127, -126), 126);
                ep1 = min(max((m1i >> 23) - 127, -126), 126);
            }
        }
#pragma unroll
        for (int u = 0; u < 4; u++) {
            emA0[u] = emB0[u]; emA1[u] = emB1[u];
            emB0[u] = nx0[u];  emB1[u] = nx1[u];
        }
    }

    // terminate: logZ = esum*ln2 + log( sum_j w_j * exp(T[STOP,j]) )
    // (final block's pending ep was never applied, so it's excluded — correct)
    float s0, s1;
    unpack2(next, s0, s1);
    s0 *= eStop;
    s1 *= eStop;
#pragma unroll
    for (int k = 16; k; k >>= 1) {
        s0 += __shfl_xor_sync(0xffffffffu, s0, k);
        s1 += __shfl_xor_sync(0xffffffffu, s1, k);
    }
    if (lane == 0) {
        out[b0] = (float)((double)esum0 * 0.6931471805599453 + log((double)s0));
        out[b1] = (float)((double)esum1 * 0.6931471805599453 + log((double)s1));
    }
}

extern "C" void kernel_launch(void* const* d_in, const int* in_sizes, int n_in,
                              void* d_out, int out_size) {
    const float* feats = (const float*)d_in[0];
    const float* trans = (const float*)d_in[1];
    float* out = (float*)d_out;
    const int B = in_sizes[0] / (SLEN * NTAGS);
    crf_fwd_kernel<<<B / 2, 32>>>(feats, trans, out);  // 2 batches per warp
}

// round 7
// speedup vs baseline: 1.3055x; 1.3055x over previous
#include <cuda_runtime.h>
#include <math.h>

#define NTAGS 32
#define SLEN 512
#define START_TAG 30
#define STOP_TAG 31

typedef unsigned long long u64;
typedef unsigned int u32;

__device__ __forceinline__ u64 pack2(float a, float b) {
    u64 r;
    asm("mov.b64 %0, {%1, %2};" : "=l"(r) : "f"(a), "f"(b));
    return r;
}
__device__ __forceinline__ void unpack2(u64 v, float &a, float &b) {
    asm("mov.b64 {%0, %1}, %2;" : "=f"(a), "=f"(b) : "l"(v));
}
__device__ __forceinline__ u64 fma2(u64 a, u64 b, u64 c) {
    u64 d;
    asm("fma.rn.f32x2 %0, %1, %2, %3;" : "=l"(d) : "l"(a), "l"(b), "l"(c));
    return d;
}
__device__ __forceinline__ u64 add2(u64 a, u64 b) {
    u64 d;
    asm("add.rn.f32x2 %0, %1, %2;" : "=l"(d) : "l"(a), "l"(b));
    return d;
}
__device__ __forceinline__ u32 smem_u32(const void* p) {
    u32 a;
    asm("{ .reg .u64 t; cvta.to.shared.u64 t, %1; cvt.u32.u64 %0, t; }"
        : "=r"(a) : "l"(p));
    return a;
}
// volatile smem ops: pins program order within the warp's LSU stream, so the
// convergent single-warp ping-pong needs no __syncwarp (validated round 6).
__device__ __forceinline__ void lds2(u64 &lo, u64 &hi, u32 addr) {
    asm volatile("ld.shared.v2.b64 {%0, %1}, [%2];"
                 : "=l"(lo), "=l"(hi) : "r"(addr));
}
__device__ __forceinline__ void sts_f32(u32 addr, float v) {
    asm volatile("st.shared.b32 [%0], %1;" :: "r"(addr), "f"(v) : "memory");
}

// One warp (= one 32-thread CTA) handles ONE batch; lane i owns target-tag i.
// f32x2 packs TAG-PAIRS (j, j+1) of the matvec, halving FMA-pipe ops while
// keeping 2048 warps (3.46/SMSP) for latency hiding. Exp-domain recurrence
// w' = (E @ w) * exp(emit). Power-of-2 renorm every 4 steps, computed via
// integer redux.max and applied ONE BLOCK LATE folded into the next block's
// pe[0] — off the serial chain. Emissions prefetched two 4-step blocks ahead.
__global__ __launch_bounds__(32)
void crf_fwd_kernel(const float* __restrict__ feats,
                    const float* __restrict__ trans,
                    float* __restrict__ out) {
    __shared__ __align__(16) float wbuf[2][NTAGS];
    const int lane = threadIdx.x;
    const int b = blockIdx.x;

    // E2[k] = {E[lane][2k], E[lane][2k+1]}, k = 0..15
    u64 E2[16];
#pragma unroll
    for (int k = 0; k < 16; k++) {
        float e0 = __expf(trans[lane * NTAGS + 2 * k]);
        float e1 = __expf(trans[lane * NTAGS + 2 * k + 1]);
        E2[k] = pack2(e0, e1);
    }
    const float eStop = __expf(trans[STOP_TAG * NTAGS + lane]);

    const u32 sb = smem_u32(&wbuf[0][0]);
    const u32 ldA = sb, ldB = sb + NTAGS * 4;
    const u32 stA = sb + lane * 4, stB = sb + NTAGS * 4 + lane * 4;

    const float* p = feats + (size_t)b * SLEN * NTAGS + lane;

    // init: alpha one-hot at START -> w one-hot (buf0)
    sts_f32(stA, (lane == START_TAG) ? 1.0f : 0.0f);
    __syncwarp();

    int esum = 0, ep = 0;  // applied + pending renorm exponents
    float emA[4], emB[4];
#pragma unroll
    for (int u = 0; u < 4; u++) {
        emA[u] = p[u * NTAGS];
        emB[u] = p[(4 + u) * NTAGS];
    }
    float nextv = 0.0f;

    for (int tb = 0; tb < SLEN; tb += 4) {
        // prefetch block tb+8 (consumed two blocks from now)
        float nx[4];
        const int nb = (tb + 8 < SLEN) ? (tb + 8) : (SLEN - 4);
#pragma unroll
        for (int u = 0; u < 4; u++)
            nx[u] = p[(nb + u) * NTAGS];

        // apply last block's renorm by folding 2^-ep into pe[0] (linear in pe)
        esum += ep;
        const float c = __int_as_float((127 - ep) << 23);  // exact 2^-ep
        float pe[4];
#pragma unroll
        for (int u = 0; u < 4; u++)
            pe[u] = __expf(emA[u]);
        pe[0] *= c;

        // 4 steps; static buffer parity (even u: buf0->buf1, odd: buf1->buf0)
#pragma unroll
        for (int u = 0; u < 4; u++) {
            const u32 ldbase = (u & 1) ? ldB : ldA;
            const u32 staddr = (u & 1) ? stA : stB;
            u64 a0 = 0, a1 = 0, a2 = 0, a3 = 0;
#pragma unroll
            for (int jj = 0; jj < 4; jj++) {
                u64 va, vb, vc, vd;
                lds2(va, vb, ldbase + jj * 16);       // w[4jj .. 4jj+3]
                lds2(vc, vd, ldbase + 64 + jj * 16);  // w[16+4jj .. 16+4jj+3]
                a0 = fma2(va, E2[2 * jj + 0], a0);
                a1 = fma2(vb, E2[2 * jj + 1], a1);
                a2 = fma2(vc, E2[8 + 2 * jj + 0], a2);
                a3 = fma2(vd, E2[8 + 2 * jj + 1], a3);
            }
            const u64 s2 = add2(add2(a0, a1), add2(a2, a3));
            float lo, hi;
            unpack2(s2, lo, hi);
            nextv = (lo + hi) * pe[u];
            sts_f32(staddr, nextv);
            if (u == 3) {
                // end-of-block max (w >= 0 => IEEE bits monotone as s32;
                // sm_103a has no redux.f32)
                int mi;
                asm("redux.sync.max.s32 %0, %1, 0xffffffff;"
                    : "=r"(mi) : "r"(__float_as_int(nextv)));
                ep = min(max((mi >> 23) - 127, -126), 126);
            }
        }
#pragma unroll
        for (int u = 0; u < 4; u++) { emA[u] = emB[u]; emB[u] = nx[u]; }
    }

    // terminate: logZ = esum*ln2 + log( sum_j w_j * exp(T[STOP,j]) )
    // (final block's pending ep was never applied to w, so excluding it is correct)
    float s = nextv * eStop;
#pragma unroll
    for (int k = 16; k; k >>= 1)
        s += __shfl_xor_sync(0xffffffffu, s, k);
    if (lane == 0)
        out[b] = (float)((double)esum * 0.6931471805599453 + log((double)s));
}

extern "C" void kernel_launch(void* const* d_in, const int* in_sizes, int n_in,
                              void* d_out, int out_size) {
    const float* feats = (const float*)d_in[0];
    const float* trans = (const float*)d_in[1];
    float* out = (float*)d_out;
    const int B = in_sizes[0] / (SLEN * NTAGS);
    crf_fwd_kernel<<<B, 32>>>(feats, trans, out);  // one warp per batch
}

// round 8
// speedup vs baseline: 1.6367x; 1.2537x over previous
#include <cuda_runtime.h>
#include <cuda_bf16.h>
#include <math.h>

#define NTAGS 32
#define SLEN 512
#define START_TAG 30
#define STOP_TAG 31

typedef unsigned int u32;
typedef unsigned short u16;

__device__ __forceinline__ u32 smem_u32(const void* p) {
    u32 a;
    asm("{ .reg .u64 t; cvta.to.shared.u64 t, %1; cvt.u32.u64 %0, t; }"
        : "=r"(a) : "l"(p));
    return a;
}
// bf16x2 pack: lo -> bits[15:0], hi -> bits[31:16]
__device__ __forceinline__ u32 pack_bf2(float lo, float hi) {
    u32 d;
    asm("cvt.rn.bf16x2.f32 %0, %1, %2;" : "=r"(d) : "f"(hi), "f"(lo));
    return d;
}
__device__ __forceinline__ u32 bfma2(u32 a, u32 b, u32 c) {
    u32 d;
    asm("fma.rn.bf16x2 %0, %1, %2, %3;" : "=r"(d) : "r"(a), "r"(b), "r"(c));
    return d;
}
__device__ __forceinline__ u32 badd2(u32 a, u32 b) {
    u32 d;
    asm("add.rn.bf16x2 %0, %1, %2;" : "=r"(d) : "r"(a), "r"(b));
    return d;
}
// volatile smem ops: program order within the single warp's LSU stream, so
// the convergent ping-pong needs no __syncwarp (validated rounds 6-7).
__device__ __forceinline__ void lds4(u32 &r0, u32 &r1, u32 &r2, u32 &r3,
                                     u32 addr) {
    asm volatile("ld.shared.v4.b32 {%0,%1,%2,%3}, [%4];"
                 : "=r"(r0), "=r"(r1), "=r"(r2), "=r"(r3) : "r"(addr));
}
__device__ __forceinline__ void sts_bf16(u32 addr, float v) {
    u16 h;
    asm("cvt.rn.bf16.f32 %0, %1;" : "=h"(h) : "f"(v));
    asm volatile("st.shared.u16 [%0], %1;" :: "r"(addr), "h"(h) : "memory");
}

// One warp (= one 32-thread CTA) handles ONE batch; lane i owns target-tag i.
// The recurrence state w is stored in smem as BF16 (64B): the smem-crossbar
// LDS dispatch (4 cyc/LDS at nw>=4) was the measured binder at fp32 (8.4M
// LDS.128 ~ 119us ~ observed wall); bf16 halves it to 4 LDS.128/step and the
// matvec to 16 bf16x2 FMAs. Exponent range of bf16 == fp32, required because
// deferred renorm lets w grow ~e^50 between applications (fp16 would overflow).
// Horizontal sum + emission multiply stay fp32 (exact shift-based bf16->f32).
// Power-of-2 renorm every 4 steps via integer redux.max, applied one block
// late folded into the next block's pe[0]. Emissions prefetched two 4-step
// blocks ahead. No per-step syncwarp.
__global__ __launch_bounds__(32)
void crf_fwd_kernel(const float* __restrict__ feats,
                    const float* __restrict__ trans,
                    float* __restrict__ out) {
    __shared__ __align__(16) u16 wbuf[2][NTAGS];
    const int lane = threadIdx.x;
    const int b = blockIdx.x;

    // E2h[k] = bf16x2 {E[lane][2k], E[lane][2k+1]}, k = 0..15
    u32 E2h[16];
#pragma unroll
    for (int k = 0; k < 16; k++) {
        float e0 = __expf(trans[lane * NTAGS + 2 * k]);
        float e1 = __expf(trans[lane * NTAGS + 2 * k + 1]);
        E2h[k] = pack_bf2(e0, e1);
    }
    const float eStop = __expf(trans[STOP_TAG * NTAGS + lane]);

    const u32 sb  = smem_u32(&wbuf[0][0]);
    const u32 ldA = sb, ldB = sb + NTAGS * 2;           // 64B buffers
    const u32 stA = sb + lane * 2, stB = sb + NTAGS * 2 + lane * 2;

    const float* p = feats + (size_t)b * SLEN * NTAGS + lane;

    // init: alpha one-hot at START -> w one-hot (buf0)
    sts_bf16(stA, (lane == START_TAG) ? 1.0f : 0.0f);
    __syncwarp();

    int esum = 0, ep = 0;  // applied + pending renorm exponents
    float emA[4], emB[4];
#pragma unroll
    for (int u = 0; u < 4; u++) {
        emA[u] = p[u * NTAGS];
        emB[u] = p[(4 + u) * NTAGS];
    }
    float nextv = 0.0f;

    for (int tb = 0; tb < SLEN; tb += 4) {
        // prefetch block tb+8 (consumed two blocks from now)
        float nx[4];
        const int nb = (tb + 8 < SLEN) ? (tb + 8) : (SLEN - 4);
#pragma unroll
        for (int u = 0; u < 4; u++)
            nx[u] = p[(nb + u) * NTAGS];

        // apply last block's renorm by folding exact 2^-ep into pe[0]
        esum += ep;
        const float c = __int_as_float((127 - ep) << 23);
        float pe[4];
#pragma unroll
        for (int u = 0; u < 4; u++)
            pe[u] = __expf(emA[u]);
        pe[0] *= c;

        // 4 steps; static buffer parity (even u: buf0->buf1, odd: buf1->buf0)
#pragma unroll
        for (int u = 0; u < 4; u++) {
            const u32 ldbase = (u & 1) ? ldB : ldA;
            const u32 staddr = (u & 1) ? stA : stB;
            // 64B of bf16 w = 4 LDS.128 broadcast -> 16 bf16x2 tag-pairs
            u32 v0, v1, v2, v3, v4, v5, v6, v7;
            u32 v8, v9, v10, v11, v12, v13, v14, v15;
            lds4(v0, v1, v2, v3, ldbase);
            lds4(v4, v5, v6, v7, ldbase + 16);
            lds4(v8, v9, v10, v11, ldbase + 32);
            lds4(v12, v13, v14, v15, ldbase + 48);
            // 4 independent bf16x2 accumulator chains of depth 4
            u32 a0 = bfma2(v0, E2h[0], 0u);
            u32 a1 = bfma2(v1, E2h[1], 0u);
            u32 a2 = bfma2(v2, E2h[2], 0u);
            u32 a3 = bfma2(v3, E2h[3], 0u);
            a0 = bfma2(v4, E2h[4], a0);
            a1 = bfma2(v5, E2h[5], a1);
            a2 = bfma2(v6, E2h[6], a2);
            a3 = bfma2(v7, E2h[7], a3);
            a0 = bfma2(v8, E2h[8], a0);
            a1 = bfma2(v9, E2h[9], a1);
            a2 = bfma2(v10, E2h[10], a2);
            a3 = bfma2(v11, E2h[11], a3);
            a0 = bfma2(v12, E2h[12], a0);
            a1 = bfma2(v13, E2h[13], a1);
            a2 = bfma2(v14, E2h[14], a2);
            a3 = bfma2(v15, E2h[15], a3);
            const u32 acc = badd2(badd2(a0, a1), badd2(a2, a3));
            // exact bf16 -> f32 via shifts (ALU pipe), horizontal add in fp32
            const float fl = __uint_as_float(acc << 16);
            const float fh = __uint_as_float(acc & 0xffff0000u);
            nextv = (fl + fh) * pe[u];
            sts_bf16(staddr, nextv);
            if (u == 3) {
                // end-of-block max (w >= 0 => IEEE bits monotone as s32;
                // sm_103a has no redux.f32)
                int mi;
                asm("redux.sync.max.s32 %0, %1, 0xffffffff;"
                    : "=r"(mi) : "r"(__float_as_int(nextv)));
                ep = min(max((mi >> 23) - 127, -126), 126);
            }
        }
#pragma unroll
        for (int u = 0; u < 4; u++) { emA[u] = emB[u]; emB[u] = nx[u]; }
    }

    // terminate: logZ = esum*ln2 + log( sum_j w_j * exp(T[STOP,j]) )
    // (final block's pending ep was never applied to w, so excluding it is correct)
    float s = nextv * eStop;
#pragma unroll
    for (int k = 16; k; k >>= 1)
        s += __shfl_xor_sync(0xffffffffu, s, k);
    if (lane == 0)
        out[b] = (float)((double)esum * 0.6931471805599453 + log((double)s));
}

extern "C" void kernel_launch(void* const* d_in, const int* in_sizes, int n_in,
                              void* d_out, int out_size) {
    const float* feats = (const float*)d_in[0];
    const float* trans = (const float*)d_in[1];
    float* out = (float*)d_out;
    const int B = in_sizes[0] / (SLEN * NTAGS);
    crf_fwd_kernel<<<B, 32>>>(feats, trans, out);  // one warp per batch
}

// round 9
// speedup vs baseline: 1.6526x; 1.0097x over previous
#include <cuda_runtime.h>
#include <math.h>

#define NTAGS 32
#define SLEN 512
#define START_TAG 30
#define STOP_TAG 31
#define NB 8   // batches per warp (rows 0..7 of the m16 tile; rows 8..15 zero)

typedef unsigned int u32;

__device__ __forceinline__ u32 pack_bf2(float lo, float hi) {
    u32 d;
    asm("cvt.rn.bf16x2.f32 %0, %1, %2;" : "=r"(d) : "f"(hi), "f"(lo));
    return d;
}

// D = A @ B (m16n8k16 bf16, fp32 accum from zero). Only rows 0..7 used:
// a1/a3 (rows 8..15) are zero; we consume d0,d1 (row = lane>>2).
__device__ __forceinline__ void mma8(float &d0, float &d1,
                                     u32 a0, u32 a2, u32 b0, u32 b1) {
    float d2, d3;
    asm("mma.sync.aligned.m16n8k16.row.col.f32.bf16.bf16.f32 "
        "{%0,%1,%2,%3}, {%4,%5,%6,%7}, {%8,%9}, {%10,%11,%12,%13};"
        : "=f"(d0), "=f"(d1), "=f"(d2), "=f"(d3)
        : "r"(a0), "r"(0u), "r"(a2), "r"(0u), "r"(b0), "r"(b1),
          "f"(0.f), "f"(0.f), "f"(0.f), "f"(0.f));
}

// One 4-step block: pe = exp(raw) (+ pending renorm folded into step 0),
// refill raw with block t0+8, run 4 MMA recurrence steps, compute new
// pending renorm exponent at the last step.
__device__ __forceinline__ void process_block(
    float2 (&raw)[4][4], const float* pb, int t0,
    u32 (&Aa)[2][2], const u32 (&Bf)[2][4][2],
    int &esum, int &pend, float (&v)[4][2], int lane)
{
    // exp of this block's emissions (loaded two blocks ago) — off-chain
    float pe[4][4][2];
#pragma unroll
    for (int u = 0; u < 4; u++)
#pragma unroll
        for (int n = 0; n < 4; n++) {
            pe[u][n][0] = __expf(raw[u][n].x);
            pe[u][n][1] = __expf(raw[u][n].y);
        }
    // refill this buffer with block t0+8 (clamped; tail refills unused)
    const int nbk = (t0 + 8 < SLEN) ? (t0 + 8) : (SLEN - 4);
#pragma unroll
    for (int u = 0; u < 4; u++)
#pragma unroll
        for (int n = 0; n < 4; n++)
            raw[u][n] = *(const float2*)(pb + (size_t)(nbk + u) * NTAGS + n * 8);

    // apply pending power-of-2 renorm by folding exact 2^-pend into step-0 pe
    esum += pend;
    const float sc = __int_as_float((127 - pend) << 23);
#pragma unroll
    for (int n = 0; n < 4; n++) { pe[0][n][0] *= sc; pe[0][n][1] *= sc; }
    pend = 0;

#pragma unroll
    for (int u = 0; u < 4; u++) {
        u32 newA[4];
#pragma unroll
        for (int n = 0; n < 4; n++) {
            float d0a, d1a, d0b, d1b;
            mma8(d0a, d1a, Aa[0][0], Aa[0][1], Bf[0][n][0], Bf[0][n][1]);
            mma8(d0b, d1b, Aa[1][0], Aa[1][1], Bf[1][n][0], Bf[1][n][1]);
            v[n][0] = (d0a + d0b) * pe[u][n][0];
            v[n][1] = (d1a + d1b) * pe[u][n][1];
            newA[n] = pack_bf2(v[n][0], v[n][1]);
        }
        // accumulator(m16n8) -> next A fragment(m16k16): tile n feeds
        // k-cols [8n, 8n+8) — the classic P-reuse identity, no shuffles.
        Aa[0][0] = newA[0]; Aa[0][1] = newA[1];
        Aa[1][0] = newA[2]; Aa[1][1] = newA[3];
        if (u == 3) {
            // row max over this lane's 8 products, then across the quad
            float m = fmaxf(fmaxf(fmaxf(v[0][0], v[0][1]),
                                  fmaxf(v[1][0], v[1][1])),
                            fmaxf(fmaxf(v[2][0], v[2][1]),
                                  fmaxf(v[3][0], v[3][1])));
            m = fmaxf(m, __shfl_xor_sync(0xffffffffu, m, 1));
            m = fmaxf(m, __shfl_xor_sync(0xffffffffu, m, 2));
            const int e = (__float_as_int(m) >> 23) - 127;
            pend = min(max(e, -126), 126);
        }
    }
}

// One warp (= one 32-thread CTA) advances 8 independent CRF chains with the
// tensor core: W'[8x32] = W @ E as m16n8k16 bf16 MMAs (4 n-tiles x 2 k-chunks,
// parallel-k). W lives entirely in A-fragment registers; E in B-fragment
// registers; NO shared memory in the recurrence (the smem crossbar was the
// measured binder of all previous rounds). Emissions are LDG.64'd directly
// into fragment positions (each quad covers a full 128B row), 2 blocks deep.
// Exp-domain + deferred exact power-of-2 renorm as validated in rounds 6-8.
__global__ __launch_bounds__(32)
void crf_fwd_kernel(const float* __restrict__ feats,
                    const float* __restrict__ trans,
                    float* __restrict__ out) {
    const int lane = threadIdx.x;
    const int g = lane >> 2;    // batch row 0..7
    const int tid = lane & 3;
    const int base = blockIdx.x * NB;

    // B fragments of E (E[j,i] = exp(trans[i,j])): Bf[kc][n][r]
    // b0 holds (k=tid*2, n=g),(k=tid*2+1, n=g); b1 same with k+8.
    u32 Bf[2][4][2];
#pragma unroll
    for (int kc = 0; kc < 2; kc++)
#pragma unroll
        for (int n = 0; n < 4; n++) {
            const int i = n * 8 + g;
            const int j0 = kc * 16 + tid * 2;
            float e0 = __expf(trans[i * NTAGS + j0]);
            float e1 = __expf(trans[i * NTAGS + j0 + 1]);
            float e2 = __expf(trans[i * NTAGS + j0 + 8]);
            float e3 = __expf(trans[i * NTAGS + j0 + 9]);
            Bf[kc][n][0] = pack_bf2(e0, e1);
            Bf[kc][n][1] = pack_bf2(e2, e3);
        }
    // stop-transition weights for this lane's 8 tag slots
    float eS[4][2];
#pragma unroll
    for (int n = 0; n < 4; n++) {
        eS[n][0] = __expf(trans[STOP_TAG * NTAGS + n * 8 + tid * 2]);
        eS[n][1] = __expf(trans[STOP_TAG * NTAGS + n * 8 + tid * 2 + 1]);
    }

    // emission base: row (base+g), tag column tid*2 (8B-aligned float2 loads)
    const float* pb = feats + (size_t)(base + g) * SLEN * NTAGS + tid * 2;

    // A fragments (bf16x2): Aa[kc][0] = cols kc*16+tid*2, Aa[kc][1] = +8.
    // init: w one-hot at tag 30 -> chunk 1, a2 slot, tid==3, lo half.
    u32 Aa[2][2] = {{0u, 0u}, {0u, (tid == 3) ? 0x00003F80u : 0u}};

    // two 4-step blocks of raw emissions in flight
    float2 rawA[4][4], rawB[4][4];
#pragma unroll
    for (int u = 0; u < 4; u++)
#pragma unroll
        for (int n = 0; n < 4; n++) {
            rawA[u][n] = *(const float2*)(pb + (size_t)u * NTAGS + n * 8);
            rawB[u][n] = *(const float2*)(pb + (size_t)(4 + u) * NTAGS + n * 8);
        }

    int esum = 0, pend = 0;
    float v[4][2];

    for (int tb = 0; tb < SLEN; tb += 8) {
        process_block(rawA, pb, tb,     Aa, Bf, esum, pend, v, lane);
        process_block(rawB, pb, tb + 4, Aa, Bf, esum, pend, v, lane);
    }

    // terminate: logZ_b = esum*ln2 + log( sum_i w[b,i] * exp(T[STOP,i]) )
    // (final block's pending exponent was never applied to w -> excluded)
    float s = 0.f;
#pragma unroll
    for (int n = 0; n < 4; n++)
        s += v[n][0] * eS[n][0] + v[n][1] * eS[n][1];
    s += __shfl_xor_sync(0xffffffffu, s, 1);
    s += __shfl_xor_sync(0xffffffffu, s, 2);
    if (tid == 0)
        out[base + g] =
            (float)((double)esum * 0.6931471805599453 + log((double)s));
}

extern "C" void kernel_launch(void* const* d_in, const int* in_sizes, int n_in,
                              void* d_out, int out_size) {
    const float* feats = (const float*)d_in[0];
    const float* trans = (const float*)d_in[1];
    float* out = (float*)d_out;
    const int B = in_sizes[0] / (SLEN * NTAGS);
    crf_fwd_kernel<<<B / NB, 32>>>(feats, trans, out);  // 8 batches per warp
}